// round 1
// baseline (speedup 1.0000x reference)
#include <cuda_runtime.h>
#include <math.h>

// Problem dims (fixed by the dataset)
#define Bz   8
#define Nz   256
#define Dz   512
#define Hz   16
#define Kz   4
#define DKz  32
#define FFNz 2048
#define Mrows 2048            // B*N
#define NEGV (-1e12f)

// -------------------- scratch (no allocations allowed) --------------------
__device__ __align__(16) float g_q   [Bz*Hz*Nz*DKz];
__device__ __align__(16) float g_k   [Bz*Hz*Nz*DKz];
__device__ __align__(16) float g_v   [Bz*Hz*Nz*DKz];
__device__ __align__(16) float g_msgT[Bz*Kz*Hz*DKz*Nz];   // [B][K][H][dk][N] == A for W1 GEMM
__device__ __align__(16) float g_s1  [Mrows*Dz];
__device__ __align__(16) float g_h   [Mrows*Dz];
__device__ __align__(16) float g_y   [Mrows*Dz];
__device__ __align__(16) float g_f1  [Mrows*FFNz];
__device__ __align__(16) float g_f2  [Mrows*Dz];

// -------------------- generic tiled SGEMM, fused epilogues --------------------
// C[M,N] = A[M,K] @ B[K,N] + bias  (+ activation / scatter)
// EPI: 0 = bias only, 1 = silu, 2 = exact gelu, 3 = bias + scatter to [B,H,N,dk]
template<int EPI>
__global__ __launch_bounds__(256, 2)
void sgemm(const float* __restrict__ A, const float* __restrict__ B,
           const float* __restrict__ bias, float* __restrict__ C,
           int M, int N, int K)
{
    __shared__ float As[16][68];   // [k][row], pad 68 to keep FP32 banks happy
    __shared__ float Bs[16][64];   // [k][col]

    const int tid  = threadIdx.x;
    const int tx   = tid & 15;
    const int ty   = tid >> 4;
    const int row0 = blockIdx.y * 64;
    const int col0 = blockIdx.x * 64;

    const int a_r = tid >> 2;          // 0..63
    const int a_k = (tid & 3) << 2;    // 0,4,8,12
    const int b_k = tid >> 4;          // 0..15
    const int b_c = (tid & 15) << 2;   // 0..60

    const float* Ap = A + (size_t)(row0 + a_r) * K + a_k;
    const float* Bp = B + (size_t)b_k * N + col0 + b_c;

    float acc[4][4] = {};

    for (int k0 = 0; k0 < K; k0 += 16) {
        float4 av = *(const float4*)Ap;
        float4 bv = *(const float4*)Bp;
        Ap += 16;
        Bp += (size_t)16 * N;
        As[a_k + 0][a_r] = av.x;
        As[a_k + 1][a_r] = av.y;
        As[a_k + 2][a_r] = av.z;
        As[a_k + 3][a_r] = av.w;
        *(float4*)&Bs[b_k][b_c] = bv;
        __syncthreads();
#pragma unroll
        for (int kk = 0; kk < 16; kk++) {
            float4 a4 = *(const float4*)&As[kk][ty * 4];
            float4 b4 = *(const float4*)&Bs[kk][tx * 4];
            float ar[4] = {a4.x, a4.y, a4.z, a4.w};
            float br[4] = {b4.x, b4.y, b4.z, b4.w};
#pragma unroll
            for (int i = 0; i < 4; i++)
#pragma unroll
                for (int j = 0; j < 4; j++)
                    acc[i][j] = fmaf(ar[i], br[j], acc[i][j]);
        }
        __syncthreads();
    }

#pragma unroll
    for (int i = 0; i < 4; i++) {
        const int r = row0 + ty * 4 + i;
#pragma unroll
        for (int j = 0; j < 4; j++) {
            const int c = col0 + tx * 4 + j;
            float vv = acc[i][j] + bias[c];
            if (EPI == 1) {                       // silu
                vv = vv / (1.f + expf(-vv));
            } else if (EPI == 2) {                // exact gelu
                vv = 0.5f * vv * (1.f + erff(vv * 0.70710678118654752f));
            }
            if (EPI == 3) {                       // scatter to [B,H,N,dk]
                const int b = r >> 8, n = r & 255, h = c >> 5, d = c & 31;
                C[(((size_t)(b * Hz + h) * Nz + n) * DKz) + d] = vv;
            } else {
                C[(size_t)r * N + c] = vv;
            }
        }
    }
}

// -------------------- attention: warp-per-row, 4 distance scales --------------------
// grid = (B*H, 4), block = 256 threads (8 warps). Each warp owns one query row n,
// computes 256 scores vs smem K, does 4 masked softmaxes fully warp-local, and
// accumulates msg via smem-transposed V with float4 reads.
// Writes msgT[b][kk][h][d][n]  (== contiguous A rows for the W1 GEMM).
__global__ __launch_bounds__(256)
void attn_kernel(const float* __restrict__ q, const float* __restrict__ k,
                 const float* __restrict__ v, const float* __restrict__ dist,
                 const float* __restrict__ dbar, const float* __restrict__ bias,
                 const int* __restrict__ mask, float* __restrict__ msgT)
{
    extern __shared__ float sh[];
    float* ks  = sh;             // 256*33  : K rows, pad 33 (conflict-free dot reads)
    float* vsT = sh + 256 * 33;  // 32*260  : V transposed [d][m], pad 260 (float4 aligned)
    float* sm  = vsT + 32 * 260; // 8*256   : per-warp probability row

    const int bh   = blockIdx.x;
    const int b    = bh >> 4;
    const int h    = bh & 15;
    const int tid  = threadIdx.x;
    const int lane = tid & 31;
    const int wid  = tid >> 5;

    const float* kb = k + (size_t)bh * (Nz * DKz);
    const float* vb = v + (size_t)bh * (Nz * DKz);
    for (int i = tid; i < Nz * DKz; i += 256) {
        const int m = i >> 5, d = i & 31;
        ks[m * 33 + d]   = kb[i];
        vsT[d * 260 + m] = vb[i];
    }
    __syncthreads();

    float dbv[4];
#pragma unroll
    for (int kk = 0; kk < 4; kk++) dbv[kk] = dbar[kk];

    const int n0 = blockIdx.y * 64;
    for (int n = n0 + wid; n < n0 + 64; n += 8) {
        // q row broadcast into registers (uniform loads, L1 hit)
        float qr[32];
        const float* qrow = q + ((size_t)bh * Nz + n) * DKz;
#pragma unroll
        for (int d = 0; d < 32; d++) qr[d] = qrow[d] * 0.17677669529663687f; // 1/sqrt(32)

        float s[8], nd[8];
        const int*   mrow = mask + ((size_t)b * Nz + n) * Nz;
        const float* drow = dist + (size_t)b * 255 * 255 + (size_t)(n - 1) * 255 - 1;
#pragma unroll
        for (int j = 0; j < 8; j++) {
            const int m = j * 32 + lane;
            float acc = 0.f;
#pragma unroll
            for (int d = 0; d < 32; d++) acc = fmaf(qr[d], ks[m * 33 + d], acc);
            s[j] = acc;
            // combined mask encoding: nd < dbar[kk]  <=>  position allowed
            float ndv;
            if (n == 0 || m == 0) ndv = -1.f;       // super-node: always allowed
            else                  ndv = drow[m];    // real distance
            if (mrow[m] == 0)     ndv = 1e30f;      // padding mask: never allowed
            nd[j] = ndv;
        }

        float*        smw   = sm + wid * 256;
        const float4* smw4  = (const float4*)smw;
        const float4* vrow4 = (const float4*)(vsT + lane * 260);

        for (int kk = 0; kk < 4; kk++) {
            const float* brow = bias + (((size_t)(b * Kz + kk) * Nz + n) * Nz);
            float e[8];
            float mx = -INFINITY;
#pragma unroll
            for (int j = 0; j < 8; j++) {
                const int m = j * 32 + lane;
                const float sc = (nd[j] < dbv[kk]) ? s[j] + brow[m] : NEGV;
                e[j] = sc;
                mx = fmaxf(mx, sc);
            }
#pragma unroll
            for (int o = 16; o > 0; o >>= 1)
                mx = fmaxf(mx, __shfl_xor_sync(0xffffffffu, mx, o));
            float sum = 0.f;
#pragma unroll
            for (int j = 0; j < 8; j++) {
                e[j] = expf(e[j] - mx);
                sum += e[j];
            }
#pragma unroll
            for (int o = 16; o > 0; o >>= 1)
                sum += __shfl_xor_sync(0xffffffffu, sum, o);
            const float inv = 1.f / sum;
#pragma unroll
            for (int j = 0; j < 8; j++)
                smw[j * 32 + lane] = e[j] * inv;
            __syncwarp();

            // msg[d=lane] = sum_m p[m] * v[m][d]   (float4 over m)
            float out = 0.f;
#pragma unroll 8
            for (int mm = 0; mm < 64; mm++) {
                const float4 a4 = smw4[mm];
                const float4 w4 = vrow4[mm];
                out = fmaf(a4.x, w4.x, out);
                out = fmaf(a4.y, w4.y, out);
                out = fmaf(a4.z, w4.z, out);
                out = fmaf(a4.w, w4.w, out);
            }
            msgT[((((size_t)(b * Kz + kk) * Hz + h) * DKz + lane) * Nz) + n] = out;
            __syncwarp();
        }
    }
}

// -------------------- residual + layernorm (row of 512) --------------------
__global__ __launch_bounds__(128)
void ln_kernel(const float* __restrict__ hbuf, const float* __restrict__ res,
               const float* __restrict__ g, const float* __restrict__ be,
               float* __restrict__ out)
{
    __shared__ float red[4];
    const int row = blockIdx.x;
    const int tid = threadIdx.x;
    const float* hp = hbuf + (size_t)row * Dz;
    const float* rp = res  + (size_t)row * Dz;

    float vv[4];
    float sum = 0.f;
#pragma unroll
    for (int i = 0; i < 4; i++) {
        vv[i] = hp[i * 128 + tid] + rp[i * 128 + tid];
        sum += vv[i];
    }
#pragma unroll
    for (int o = 16; o > 0; o >>= 1) sum += __shfl_xor_sync(0xffffffffu, sum, o);
    if ((tid & 31) == 0) red[tid >> 5] = sum;
    __syncthreads();
    const float mean = (red[0] + red[1] + red[2] + red[3]) * (1.f / 512.f);

    float var = 0.f;
#pragma unroll
    for (int i = 0; i < 4; i++) { const float t = vv[i] - mean; var += t * t; }
#pragma unroll
    for (int o = 16; o > 0; o >>= 1) var += __shfl_xor_sync(0xffffffffu, var, o);
    __syncthreads();
    if ((tid & 31) == 0) red[tid >> 5] = var;
    __syncthreads();
    var = (red[0] + red[1] + red[2] + red[3]) * (1.f / 512.f);
    const float rstd = rsqrtf(var + 1e-6f);

#pragma unroll
    for (int i = 0; i < 4; i++) {
        const int c = i * 128 + tid;
        out[(size_t)row * Dz + c] = (vv[i] - mean) * rstd * g[c] + be[c];
    }
}

// -------------------- launcher --------------------
extern "C" void kernel_launch(void* const* d_in, const int* in_sizes, int n_in,
                              void* d_out, int out_size)
{
    const float* x    = (const float*)d_in[0];
    const float* dist = (const float*)d_in[1];
    const float* dbar = (const float*)d_in[2];
    const float* bias = (const float*)d_in[3];
    const int*   mask = (const int*)d_in[4];
    // d_in[5] may be the num_heads scalar; weights start at 6 in that case.
    const int off = (in_sizes[5] == 1) ? 6 : 5;
    const float* Wq  = (const float*)d_in[off + 0];
    const float* bq  = (const float*)d_in[off + 1];
    const float* Wk  = (const float*)d_in[off + 2];
    const float* bk  = (const float*)d_in[off + 3];
    const float* Wv  = (const float*)d_in[off + 4];
    const float* bv  = (const float*)d_in[off + 5];
    const float* W1  = (const float*)d_in[off + 6];
    const float* b1  = (const float*)d_in[off + 7];
    const float* W2  = (const float*)d_in[off + 8];
    const float* b2  = (const float*)d_in[off + 9];
    const float* g1  = (const float*)d_in[off + 10];
    const float* be1 = (const float*)d_in[off + 11];
    const float* Wf1 = (const float*)d_in[off + 12];
    const float* bf1 = (const float*)d_in[off + 13];
    const float* Wf2 = (const float*)d_in[off + 14];
    const float* bf2 = (const float*)d_in[off + 15];
    const float* g2  = (const float*)d_in[off + 16];
    const float* be2 = (const float*)d_in[off + 17];
    float* out = (float*)d_out;

    float *q, *k, *v, *msgT, *s1, *hh, *y, *f1, *f2;
    cudaGetSymbolAddress((void**)&q,    g_q);
    cudaGetSymbolAddress((void**)&k,    g_k);
    cudaGetSymbolAddress((void**)&v,    g_v);
    cudaGetSymbolAddress((void**)&msgT, g_msgT);
    cudaGetSymbolAddress((void**)&s1,   g_s1);
    cudaGetSymbolAddress((void**)&hh,   g_h);
    cudaGetSymbolAddress((void**)&y,    g_y);
    cudaGetSymbolAddress((void**)&f1,   g_f1);
    cudaGetSymbolAddress((void**)&f2,   g_f2);

    const int ATTN_SMEM = (256 * 33 + 32 * 260 + 8 * 256) * (int)sizeof(float); // 75264 B
    cudaFuncSetAttribute(attn_kernel, cudaFuncAttributeMaxDynamicSharedMemorySize, ATTN_SMEM);

    // 1) QKV projections -> [B,H,N,dk]
    {
        dim3 grid(Dz / 64, Mrows / 64);
        sgemm<3><<<grid, 256>>>(x, Wq, bq, q, Mrows, Dz, Dz);
        sgemm<3><<<grid, 256>>>(x, Wk, bk, k, Mrows, Dz, Dz);
        sgemm<3><<<grid, 256>>>(x, Wv, bv, v, Mrows, Dz, Dz);
    }

    // 2) multi-scale masked attention -> msgT [B,K,H,dk,N]
    {
        dim3 grid(Bz * Hz, 4);
        attn_kernel<<<grid, 256, ATTN_SMEM>>>(q, k, v, dist, dbar, bias, mask, msgT);
    }

    // 3) silu(msgT @ W1 + b1) -> s1 [2048,512]
    sgemm<1><<<dim3(Dz / 64, Mrows / 64), 256>>>(msgT, W1, b1, s1, Mrows, Dz, Kz * Dz);

    // 4) s1 @ W2 + b2 -> h
    sgemm<0><<<dim3(Dz / 64, Mrows / 64), 256>>>(s1, W2, b2, hh, Mrows, Dz, Dz);

    // 5) y = LN(h + x)
    ln_kernel<<<Mrows, 128>>>(hh, x, g1, be1, y);

    // 6) gelu(y @ Wf1 + bf1) -> f1 [2048,2048]
    sgemm<2><<<dim3(FFNz / 64, Mrows / 64), 256>>>(y, Wf1, bf1, f1, Mrows, FFNz, Dz);

    // 7) f1 @ Wf2 + bf2 -> f2
    sgemm<0><<<dim3(Dz / 64, Mrows / 64), 256>>>(f1, Wf2, bf2, f2, Mrows, Dz, FFNz);

    // 8) out = LN(f2 + y)
    ln_kernel<<<Mrows, 128>>>(f2, y, g2, be2, out);
}

// round 2
// speedup vs baseline: 1.1542x; 1.1542x over previous
#include <cuda_runtime.h>
#include <math.h>

// Problem dims (fixed by the dataset)
#define Bz   8
#define Nz   256
#define Dz   512
#define Hz   16
#define Kz   4
#define DKz  32
#define FFNz 2048
#define Mrows 2048            // B*N
#define NEGV (-1e12f)

// -------------------- scratch (no allocations allowed) --------------------
__device__ __align__(16) float g_q   [Bz*Hz*Nz*DKz];
__device__ __align__(16) float g_k   [Bz*Hz*Nz*DKz];
__device__ __align__(16) float g_v   [Bz*Hz*Nz*DKz];
__device__ __align__(16) float g_msgT[Bz*Kz*Hz*DKz*Nz];   // [B][K][H][dk][N] == A for W1 GEMM
__device__ __align__(16) float g_s1  [Mrows*Dz];
__device__ __align__(16) float g_h   [Mrows*Dz];
__device__ __align__(16) float g_y   [Mrows*Dz];
__device__ __align__(16) float g_f1  [Mrows*FFNz];
__device__ __align__(16) float g_f2  [Mrows*Dz];

// -------------------- generic tiled SGEMM, fused epilogues --------------------
// C[M,N] = A[M,K] @ B[K,N] + bias  (+ activation / scatter)
// EPI: 0 = bias only, 1 = silu, 2 = exact gelu, 3 = bias + scatter to [B,H,N,dk]
template<int EPI>
__global__ __launch_bounds__(256, 2)
void sgemm(const float* __restrict__ A, const float* __restrict__ B,
           const float* __restrict__ bias, float* __restrict__ C,
           int M, int N, int K)
{
    __shared__ float As[16][68];
    __shared__ float Bs[16][64];

    const int tid  = threadIdx.x;
    const int tx   = tid & 15;
    const int ty   = tid >> 4;
    const int row0 = blockIdx.y * 64;
    const int col0 = blockIdx.x * 64;

    const int a_r = tid >> 2;          // 0..63
    const int a_k = (tid & 3) << 2;    // 0,4,8,12
    const int b_k = tid >> 4;          // 0..15
    const int b_c = (tid & 15) << 2;   // 0..60

    const float* Ap = A + (size_t)(row0 + a_r) * K + a_k;
    const float* Bp = B + (size_t)b_k * N + col0 + b_c;

    float acc[4][4] = {};

    for (int k0 = 0; k0 < K; k0 += 16) {
        float4 av = *(const float4*)Ap;
        float4 bv = *(const float4*)Bp;
        Ap += 16;
        Bp += (size_t)16 * N;
        As[a_k + 0][a_r] = av.x;
        As[a_k + 1][a_r] = av.y;
        As[a_k + 2][a_r] = av.z;
        As[a_k + 3][a_r] = av.w;
        *(float4*)&Bs[b_k][b_c] = bv;
        __syncthreads();
#pragma unroll
        for (int kk = 0; kk < 16; kk++) {
            float4 a4 = *(const float4*)&As[kk][ty * 4];
            float4 b4 = *(const float4*)&Bs[kk][tx * 4];
            float ar[4] = {a4.x, a4.y, a4.z, a4.w};
            float br[4] = {b4.x, b4.y, b4.z, b4.w};
#pragma unroll
            for (int i = 0; i < 4; i++)
#pragma unroll
                for (int j = 0; j < 4; j++)
                    acc[i][j] = fmaf(ar[i], br[j], acc[i][j]);
        }
        __syncthreads();
    }

#pragma unroll
    for (int i = 0; i < 4; i++) {
        const int r = row0 + ty * 4 + i;
#pragma unroll
        for (int j = 0; j < 4; j++) {
            const int c = col0 + tx * 4 + j;
            float vv = acc[i][j] + bias[c];
            if (EPI == 1) {                       // silu
                vv = vv / (1.f + expf(-vv));
            } else if (EPI == 2) {                // exact gelu
                vv = 0.5f * vv * (1.f + erff(vv * 0.70710678118654752f));
            }
            if (EPI == 3) {                       // scatter to [B,H,N,dk]
                const int b = r >> 8, n = r & 255, h = c >> 5, d = c & 31;
                C[(((size_t)(b * Hz + h) * Nz + n) * DKz) + d] = vv;
            } else {
                C[(size_t)r * N + c] = vv;
            }
        }
    }
}

// -------------------- attention v2: block-cooperative PV GEMM --------------------
// grid = (B*H, 8), block = 256 threads. Block owns 32 query rows of one (b,h).
// Phase 1: warp w computes raw scores for rows {4w..4w+3} (256-wide, lane = m%32).
// Phase 2 (per kk): each warp normalizes its 4 rows -> smem P[32][260]; then the
// whole block computes the 32x32 PV tile with a 2x2 register tile per thread
// (rows {ty, ty+16} x dims {tx, tx+16}); V is read once per (block, kk).
// Writes msgT[b][kk][h][d][n].
__global__ __launch_bounds__(256, 2)
void attn_kernel(const float* __restrict__ q, const float* __restrict__ k,
                 const float* __restrict__ v, const float* __restrict__ dist,
                 const float* __restrict__ dbar, const float* __restrict__ bias,
                 const int* __restrict__ mask, float* __restrict__ msgT)
{
    extern __shared__ float sh[];
    float* ks  = sh;                    // 256*33 : K rows, pad 33 (conflict-free dots)
    float* vsT = sh + 256 * 33;         // 32*260 : V^T [d][m], float4-aligned rows
    float* P   = vsT + 32 * 260;        // 32*260 : probability tile for current kk

    const int bh   = blockIdx.x;
    const int b    = bh >> 4;
    const int h    = bh & 15;
    const int n0   = blockIdx.y * 32;
    const int tid  = threadIdx.x;
    const int lane = tid & 31;
    const int wid  = tid >> 5;
    const int tx   = tid & 15;
    const int ty   = tid >> 4;

    const float* kb = k + (size_t)bh * (Nz * DKz);
    const float* vb = v + (size_t)bh * (Nz * DKz);
    for (int i = tid; i < Nz * DKz; i += 256) {
        const int m = i >> 5, d = i & 31;
        ks[m * 33 + d]   = kb[i];
        vsT[d * 260 + m] = vb[i];
    }
    __syncthreads();

    float dbv[4];
#pragma unroll
    for (int kk = 0; kk < 4; kk++) dbv[kk] = dbar[kk];

    // ---- phase 1: scores for this warp's 4 rows ----
    float s[4][8], nd[4][8];
#pragma unroll
    for (int r = 0; r < 4; r++) {
        const int n = n0 + wid * 4 + r;
        const float* qrow = q + ((size_t)bh * Nz + n) * DKz;
        float qr[32];
        const float4* q4 = (const float4*)qrow;
#pragma unroll
        for (int d4 = 0; d4 < 8; d4++) {
            float4 t = q4[d4];
            qr[d4 * 4 + 0] = t.x * 0.17677669529663687f;
            qr[d4 * 4 + 1] = t.y * 0.17677669529663687f;
            qr[d4 * 4 + 2] = t.z * 0.17677669529663687f;
            qr[d4 * 4 + 3] = t.w * 0.17677669529663687f;
        }
        const int*   mrow = mask + ((size_t)b * Nz + n) * Nz;
        const float* drow = dist + (size_t)b * 255 * 255 + (size_t)(n - 1) * 255 - 1;
#pragma unroll
        for (int j = 0; j < 8; j++) {
            const int m = j * 32 + lane;
            float acc = 0.f;
#pragma unroll
            for (int d = 0; d < 32; d++) acc = fmaf(qr[d], ks[m * 33 + d], acc);
            s[r][j] = acc;
            float ndv;
            if (n == 0 || m == 0) ndv = -1.f;       // super-node: always allowed
            else                  ndv = drow[m];
            if (mrow[m] == 0)     ndv = 1e30f;      // padding: never allowed
            nd[r][j] = ndv;
        }
    }

    const int r0 = ty, r1 = ty + 16;
    const int d0 = tx, d1 = tx + 16;
    const float4* pr0 = (const float4*)(P + r0 * 260);
    const float4* pr1 = (const float4*)(P + r1 * 260);
    const float4* vd0 = (const float4*)(vsT + d0 * 260);
    const float4* vd1 = (const float4*)(vsT + d1 * 260);

    // ---- phase 2: per-scale softmax + block PV ----
    for (int kk = 0; kk < 4; kk++) {
        const float db = dbv[kk];
#pragma unroll
        for (int r = 0; r < 4; r++) {
            const int n = n0 + wid * 4 + r;
            const float* brow = bias + (((size_t)(b * Kz + kk) * Nz + n) * Nz);
            float e[8];
            float mx = -INFINITY;
#pragma unroll
            for (int j = 0; j < 8; j++) {
                const int m = j * 32 + lane;
                const float sc = (nd[r][j] < db) ? s[r][j] + brow[m] : NEGV;
                e[j] = sc;
                mx = fmaxf(mx, sc);
            }
#pragma unroll
            for (int o = 16; o > 0; o >>= 1)
                mx = fmaxf(mx, __shfl_xor_sync(0xffffffffu, mx, o));
            float sum = 0.f;
#pragma unroll
            for (int j = 0; j < 8; j++) {
                e[j] = expf(e[j] - mx);
                sum += e[j];
            }
#pragma unroll
            for (int o = 16; o > 0; o >>= 1)
                sum += __shfl_xor_sync(0xffffffffu, sum, o);
            const float inv = 1.f / sum;
#pragma unroll
            for (int j = 0; j < 8; j++)
                P[(wid * 4 + r) * 260 + j * 32 + lane] = e[j] * inv;
        }
        __syncthreads();

        // PV: 2x2 register tile per thread, V read once per (block, kk)
        float a00 = 0.f, a01 = 0.f, a10 = 0.f, a11 = 0.f;
#pragma unroll 4
        for (int mc = 0; mc < 64; mc++) {
            const float4 p0 = pr0[mc];
            const float4 p1 = pr1[mc];
            const float4 w0 = vd0[mc];
            const float4 w1 = vd1[mc];
            a00 = fmaf(p0.x, w0.x, a00); a00 = fmaf(p0.y, w0.y, a00);
            a00 = fmaf(p0.z, w0.z, a00); a00 = fmaf(p0.w, w0.w, a00);
            a01 = fmaf(p0.x, w1.x, a01); a01 = fmaf(p0.y, w1.y, a01);
            a01 = fmaf(p0.z, w1.z, a01); a01 = fmaf(p0.w, w1.w, a01);
            a10 = fmaf(p1.x, w0.x, a10); a10 = fmaf(p1.y, w0.y, a10);
            a10 = fmaf(p1.z, w0.z, a10); a10 = fmaf(p1.w, w0.w, a10);
            a11 = fmaf(p1.x, w1.x, a11); a11 = fmaf(p1.y, w1.y, a11);
            a11 = fmaf(p1.z, w1.z, a11); a11 = fmaf(p1.w, w1.w, a11);
        }

        float* ob = msgT + ((((size_t)(b * Kz + kk) * Hz + h) * DKz)) * Nz;
        ob[(size_t)d0 * Nz + n0 + r0] = a00;
        ob[(size_t)d1 * Nz + n0 + r0] = a01;
        ob[(size_t)d0 * Nz + n0 + r1] = a10;
        ob[(size_t)d1 * Nz + n0 + r1] = a11;
        __syncthreads();   // P reused next kk
    }
}

// -------------------- residual + layernorm (row of 512) --------------------
__global__ __launch_bounds__(128)
void ln_kernel(const float* __restrict__ hbuf, const float* __restrict__ res,
               const float* __restrict__ g, const float* __restrict__ be,
               float* __restrict__ out)
{
    __shared__ float red[4];
    const int row = blockIdx.x;
    const int tid = threadIdx.x;
    const float* hp = hbuf + (size_t)row * Dz;
    const float* rp = res  + (size_t)row * Dz;

    float vv[4];
    float sum = 0.f;
#pragma unroll
    for (int i = 0; i < 4; i++) {
        vv[i] = hp[i * 128 + tid] + rp[i * 128 + tid];
        sum += vv[i];
    }
#pragma unroll
    for (int o = 16; o > 0; o >>= 1) sum += __shfl_xor_sync(0xffffffffu, sum, o);
    if ((tid & 31) == 0) red[tid >> 5] = sum;
    __syncthreads();
    const float mean = (red[0] + red[1] + red[2] + red[3]) * (1.f / 512.f);

    float var = 0.f;
#pragma unroll
    for (int i = 0; i < 4; i++) { const float t = vv[i] - mean; var += t * t; }
#pragma unroll
    for (int o = 16; o > 0; o >>= 1) var += __shfl_xor_sync(0xffffffffu, var, o);
    __syncthreads();
    if ((tid & 31) == 0) red[tid >> 5] = var;
    __syncthreads();
    var = (red[0] + red[1] + red[2] + red[3]) * (1.f / 512.f);
    const float rstd = rsqrtf(var + 1e-6f);

#pragma unroll
    for (int i = 0; i < 4; i++) {
        const int c = i * 128 + tid;
        out[(size_t)row * Dz + c] = (vv[i] - mean) * rstd * g[c] + be[c];
    }
}

// -------------------- launcher --------------------
extern "C" void kernel_launch(void* const* d_in, const int* in_sizes, int n_in,
                              void* d_out, int out_size)
{
    const float* x    = (const float*)d_in[0];
    const float* dist = (const float*)d_in[1];
    const float* dbar = (const float*)d_in[2];
    const float* bias = (const float*)d_in[3];
    const int*   mask = (const int*)d_in[4];
    const int off = (in_sizes[5] == 1) ? 6 : 5;
    const float* Wq  = (const float*)d_in[off + 0];
    const float* bq  = (const float*)d_in[off + 1];
    const float* Wk  = (const float*)d_in[off + 2];
    const float* bk  = (const float*)d_in[off + 3];
    const float* Wv  = (const float*)d_in[off + 4];
    const float* bv  = (const float*)d_in[off + 5];
    const float* W1  = (const float*)d_in[off + 6];
    const float* b1  = (const float*)d_in[off + 7];
    const float* W2  = (const float*)d_in[off + 8];
    const float* b2  = (const float*)d_in[off + 9];
    const float* g1  = (const float*)d_in[off + 10];
    const float* be1 = (const float*)d_in[off + 11];
    const float* Wf1 = (const float*)d_in[off + 12];
    const float* bf1 = (const float*)d_in[off + 13];
    const float* Wf2 = (const float*)d_in[off + 14];
    const float* bf2 = (const float*)d_in[off + 15];
    const float* g2  = (const float*)d_in[off + 16];
    const float* be2 = (const float*)d_in[off + 17];
    float* out = (float*)d_out;

    float *q, *k, *v, *msgT, *s1, *hh, *y, *f1, *f2;
    cudaGetSymbolAddress((void**)&q,    g_q);
    cudaGetSymbolAddress((void**)&k,    g_k);
    cudaGetSymbolAddress((void**)&v,    g_v);
    cudaGetSymbolAddress((void**)&msgT, g_msgT);
    cudaGetSymbolAddress((void**)&s1,   g_s1);
    cudaGetSymbolAddress((void**)&hh,   g_h);
    cudaGetSymbolAddress((void**)&y,    g_y);
    cudaGetSymbolAddress((void**)&f1,   g_f1);
    cudaGetSymbolAddress((void**)&f2,   g_f2);

    const int ATTN_SMEM = (256 * 33 + 32 * 260 + 32 * 260) * (int)sizeof(float); // 100352 B
    cudaFuncSetAttribute(attn_kernel, cudaFuncAttributeMaxDynamicSharedMemorySize, ATTN_SMEM);

    // 1) QKV projections -> [B,H,N,dk]
    {
        dim3 grid(Dz / 64, Mrows / 64);
        sgemm<3><<<grid, 256>>>(x, Wq, bq, q, Mrows, Dz, Dz);
        sgemm<3><<<grid, 256>>>(x, Wk, bk, k, Mrows, Dz, Dz);
        sgemm<3><<<grid, 256>>>(x, Wv, bv, v, Mrows, Dz, Dz);
    }

    // 2) multi-scale masked attention -> msgT [B,K,H,dk,N]
    {
        dim3 grid(Bz * Hz, Nz / 32);
        attn_kernel<<<grid, 256, ATTN_SMEM>>>(q, k, v, dist, dbar, bias, mask, msgT);
    }

    // 3) silu(msgT @ W1 + b1) -> s1 [2048,512]
    sgemm<1><<<dim3(Dz / 64, Mrows / 64), 256>>>(msgT, W1, b1, s1, Mrows, Dz, Kz * Dz);

    // 4) s1 @ W2 + b2 -> h
    sgemm<0><<<dim3(Dz / 64, Mrows / 64), 256>>>(s1, W2, b2, hh, Mrows, Dz, Dz);

    // 5) y = LN(h + x)
    ln_kernel<<<Mrows, 128>>>(hh, x, g1, be1, y);

    // 6) gelu(y @ Wf1 + bf1) -> f1 [2048,2048]
    sgemm<2><<<dim3(FFNz / 64, Mrows / 64), 256>>>(y, Wf1, bf1, f1, Mrows, FFNz, Dz);

    // 7) f1 @ Wf2 + bf2 -> f2
    sgemm<0><<<dim3(Dz / 64, Mrows / 64), 256>>>(f1, Wf2, bf2, f2, Mrows, Dz, FFNz);

    // 8) out = LN(f2 + y)
    ln_kernel<<<Mrows, 128>>>(f2, y, g2, be2, out);
}